// round 17
// baseline (speedup 1.0000x reference)
#include <cuda_runtime.h>
#include <cstdint>

// PoseLSTM v15: barrier-free warp-autonomous wavefront.
//   warp = (layer l, 4 batch elements); 2560 warps, all resident, NO block
//   barriers ever. Own-h recurrence: SMEM + __syncwarp (per-warp private).
//   Layer l -> l+1 handoff: 8-step chunks through a static __device__ hbuf,
//   per-(layer,group) GMEM counters (producer fence+atomicExch, consumer
//   lane0 spin + __nanosleep). Flags zeroed by a leading reset kernel so the
//   launch is replay-safe. Lane = (u, gp) [20 active]: 2 gate rows k-packed
//   f32x2 (sigmoid 0.5 folded), 4 elems/lane-step, cell-finish 2 elems.

#define T_ 1024
#define B_ 1024
#define L_ 10
#define H_ 10
#define BH (B_ * H_)
#define CH 8
#define NCH (T_ / CH)       // 128 chunks
#define NBW 4               // elements per warp
#define WPB 4               // warps per block
#define NTH (32 * WPB)
#define NGRP (B_ / NBW)     // 256 element groups
#define BPL (NGRP / WPB)    // 64 blocks per layer

typedef unsigned long long u64;

__device__ float g_hbuf[(size_t)(L_ - 1) * T_ * B_ * H_];   // inter-layer h
__device__ int   g_cnt[(L_ - 1) * NGRP];                    // chunk counters

__device__ __forceinline__ u64 pk2(float lo, float hi) {
    u64 r; asm("mov.b64 %0, {%1,%2};" : "=l"(r) : "f"(lo), "f"(hi)); return r;
}
__device__ __forceinline__ void upk2(u64 v, float& lo, float& hi) {
    asm("mov.b64 {%0,%1}, %2;" : "=f"(lo), "=f"(hi) : "l"(v));
}
__device__ __forceinline__ u64 fma2(u64 a, u64 b, u64 c) {
    u64 d; asm("fma.rn.f32x2 %0, %1, %2, %3;" : "=l"(d) : "l"(a), "l"(b), "l"(c));
    return d;
}
__device__ __forceinline__ u64 mul2(u64 a, u64 b) {
    u64 d; asm("mul.rn.f32x2 %0, %1, %2;" : "=l"(d) : "l"(a), "l"(b));
    return d;
}
__device__ __forceinline__ u64 add2(u64 a, u64 b) {
    u64 d; asm("add.rn.f32x2 %0, %1, %2;" : "=l"(d) : "l"(a), "l"(b));
    return d;
}
__device__ __forceinline__ float tanhap(float x) {
    float r; asm("tanh.approx.f32 %0, %1;" : "=f"(r) : "f"(x)); return r;
}

// one element's 2 gate rows: 4 chains, bias pre-folded
__device__ __forceinline__ void matvec2(const ulonglong2* zz,
                                        const u64* wA, const u64* wB,
                                        u64 biasA2, u64 biasB2,
                                        float& pA, float& pB) {
    ulonglong2 v0 = zz[0], v1 = zz[1], v2 = zz[2], v3 = zz[3], v4 = zz[4];
    u64 a  = fma2(wA[0], v0.x, biasA2);
    u64 a_ = mul2(wA[1], v0.y);
    u64 b  = fma2(wB[0], v0.x, biasB2);
    u64 b_ = mul2(wB[1], v0.y);
    a  = fma2(wA[2], v1.x, a);  a_ = fma2(wA[3], v1.y, a_);
    b  = fma2(wB[2], v1.x, b);  b_ = fma2(wB[3], v1.y, b_);
    a  = fma2(wA[4], v2.x, a);  a_ = fma2(wA[5], v2.y, a_);
    b  = fma2(wB[4], v2.x, b);  b_ = fma2(wB[5], v2.y, b_);
    a  = fma2(wA[6], v3.x, a);  a_ = fma2(wA[7], v3.y, a_);
    b  = fma2(wB[6], v3.x, b);  b_ = fma2(wB[7], v3.y, b_);
    a  = fma2(wA[8], v4.x, a);  a_ = fma2(wA[9], v4.y, a_);
    b  = fma2(wB[8], v4.x, b);  b_ = fma2(wB[9], v4.y, b_);
    u64 sA = add2(a, a_), sB = add2(b, b_);
    float lo, hi;
    upk2(sA, lo, hi); pA = lo + hi;
    upk2(sB, lo, hi); pB = lo + hi;
}

__global__ void reset_cnt_kernel() {
    int i = blockIdx.x * blockDim.x + threadIdx.x;
    if (i < (L_ - 1) * NGRP) g_cnt[i] = 0;
}

__global__ __launch_bounds__(NTH, 5)
void lstm_pipe15(const float* __restrict__ x,   // (T,B,H)
                 const float* __restrict__ hp,  // (L,B,H)
                 const float* __restrict__ cp,  // (L,B,H)
                 const float* __restrict__ Wih, // (L,4H,H)
                 const float* __restrict__ Whh, // (L,4H,H)
                 const float* __restrict__ bih, // (L,4H)
                 const float* __restrict__ bhh, // (L,4H)
                 float* __restrict__ out)       // ys ++ hn ++ cn
{
    // per-warp private z: [buf][elem][24] (x-below 0..9, own h 10..19)
    __shared__ __align__(16) float z[WPB][2][NBW][24];   // 3072 B

    const int w    = threadIdx.x >> 5;
    const int lane = threadIdx.x & 31;
    const int l    = blockIdx.x / BPL;          // layer
    const int bb   = blockIdx.x % BPL;
    const int g    = bb * WPB + w;              // element group 0..255
    const int b0   = g * NBW;
    const bool act = (lane < 20);
    const int u    = act ? (lane >> 1) : 0;
    const int gp   = lane & 1;
    const int m0   = gp * 2;                    // my elems: m0, m0+1
    const int m1   = m0 + 1;

    float (*zw)[NBW][24] = z[w];

    // ---- weights: rows (i,f) for gp0, (g~,o) for gp1; sigmoid 0.5 folded ----
    const int rowA = l * 40 + gp * 20 + u;
    const int rowB = rowA + 10;
    const float sclA = gp ? 1.0f : 0.5f;
    u64 wA[10], wB[10];
    {
        const float* WiA = Wih + rowA * 10; const float* WhA = Whh + rowA * 10;
        const float* WiB = Wih + rowB * 10; const float* WhB = Whh + rowB * 10;
#pragma unroll
        for (int k = 0; k < 5; ++k) {
            wA[k]     = pk2(sclA * __ldg(WiA + 2 * k), sclA * __ldg(WiA + 2 * k + 1));
            wA[5 + k] = pk2(sclA * __ldg(WhA + 2 * k), sclA * __ldg(WhA + 2 * k + 1));
            wB[k]     = pk2(0.5f * __ldg(WiB + 2 * k), 0.5f * __ldg(WiB + 2 * k + 1));
            wB[5 + k] = pk2(0.5f * __ldg(WhB + 2 * k), 0.5f * __ldg(WhB + 2 * k + 1));
        }
    }
    const u64 biasA2 = pk2(sclA * (bih[rowA] + bhh[rowA]), 0.0f);
    const u64 biasB2 = pk2(0.5f * (bih[rowB] + bhh[rowB]), 0.0f);
    const float cAa = gp ? 0.0f : 0.5f;
    const float cBa = gp ? 1.0f : 0.5f;

    // ---- source / destination / flags ----
    const float* srcL = (l == 0) ? x : (g_hbuf + (size_t)(l - 1) * T_ * BH);
    float* dstL = (l == L_ - 1) ? out : (g_hbuf + (size_t)l * T_ * BH);
    int* waitc = (l > 0)      ? &g_cnt[(l - 1) * NGRP + g] : (int*)0;
    int* postc = (l < L_ - 1) ? &g_cnt[l * NGRP + g]       : (int*)0;

    // x-staging slot for this lane (2 consecutive floats of the 40)
    const int exE = act ? ((2 * lane) / 10) : 0;
    const int exJ = act ? ((2 * lane) % 10) : 0;

    // ---- init state ----
    float cm0 = 0.0f, cm1 = 0.0f;
    if (act) {
        cm0 = cp[(l * B_ + b0 + m0) * H_ + u];
        cm1 = cp[(l * B_ + b0 + m1) * H_ + u];
        zw[0][m0][10 + u] = hp[(l * B_ + b0 + m0) * H_ + u];
        zw[0][m1][10 + u] = hp[(l * B_ + b0 + m1) * H_ + u];
    }
    __syncwarp();

    const size_t base_hn = (size_t)T_ * BH;
    const size_t base_cn = base_hn + (size_t)L_ * BH;

    for (int c = 0; c < NCH; ++c) {
        // wait for producer to finish chunk c
        if (l > 0) {
            if (lane == 0)
                while (atomicAdd(waitc, 0) < c + 1) __nanosleep(200);
            __syncwarp();
            __threadfence();
        }
        // stage x-below for t0 = c*8 into buffer 0
        if (act) {
            const float2 v = *reinterpret_cast<const float2*>(
                srcL + (size_t)(c * CH) * BH + b0 * H_ + 2 * lane);
            *reinterpret_cast<float2*>(&zw[0][exE][exJ]) = v;
        }
        __syncwarp();

        const bool lastC = (c == NCH - 1);

#pragma unroll
        for (int j = 0; j < CH; ++j) {
            const int t = c * CH + j;
            const int cur = j & 1, nxt = cur ^ 1;

            // prefetch x-below for t+1 (within chunk)
            float2 xpre;
            if (j < CH - 1 && act)
                xpre = *reinterpret_cast<const float2*>(
                    srcL + (size_t)(t + 1) * BH + b0 * H_ + 2 * lane);

            // ---- gates for all 4 elements ----
            float pA0, pB0, pA1, pB1, pA2, pB2, pA3, pB3;
            matvec2(reinterpret_cast<const ulonglong2*>(&zw[cur][0][0]),
                    wA, wB, biasA2, biasB2, pA0, pB0);
            matvec2(reinterpret_cast<const ulonglong2*>(&zw[cur][1][0]),
                    wA, wB, biasA2, biasB2, pA1, pB1);
            matvec2(reinterpret_cast<const ulonglong2*>(&zw[cur][2][0]),
                    wA, wB, biasA2, biasB2, pA2, pB2);
            matvec2(reinterpret_cast<const ulonglong2*>(&zw[cur][3][0]),
                    wA, wB, biasA2, biasB2, pA3, pB3);

            float vA0 = fmaf(cAa == 0.0f ? 1.0f : cBa, 0.0f, 0.0f); // placeholder opt-out
            vA0 = fmaf(cBa, tanhap(pA0), cAa);
            float vB0 = fmaf(0.5f, tanhap(pB0), 0.5f);
            float vA1 = fmaf(cBa, tanhap(pA1), cAa);
            float vB1 = fmaf(0.5f, tanhap(pB1), 0.5f);
            float vA2 = fmaf(cBa, tanhap(pA2), cAa);
            float vB2 = fmaf(0.5f, tanhap(pB2), 0.5f);
            float vA3 = fmaf(cBa, tanhap(pA3), cAa);
            float vB3 = fmaf(0.5f, tanhap(pB3), 0.5f);

            // exchange with pair partner: ship partner's elems, keep mine
            const float sndA0 = gp ? vA0 : vA2;   // partner's first elem gateA
            const float sndA1 = gp ? vA1 : vA3;
            const float sndB0 = gp ? vB0 : vB2;
            const float sndB1 = gp ? vB1 : vB3;
            const float rcvA0 = __shfl_xor_sync(0xFFFFFFFFu, sndA0, 1);
            const float rcvA1 = __shfl_xor_sync(0xFFFFFFFFu, sndA1, 1);
            const float rcvB0 = __shfl_xor_sync(0xFFFFFFFFu, sndB0, 1);
            const float rcvB1 = __shfl_xor_sync(0xFFFFFFFFu, sndB1, 1);

            const float myA0 = gp ? vA2 : vA0;    // gateA of my elem m0
            const float myA1 = gp ? vA3 : vA1;
            const float myB0 = gp ? vB2 : vB0;
            const float myB1 = gp ? vB3 : vB1;

            const float F0 = gp ? rcvB0 : myB0;
            const float O0 = gp ? myB0  : rcvB0;
            const float F1 = gp ? rcvB1 : myB1;
            const float O1 = gp ? myB1  : rcvB1;

            cm0 = fmaf(F0, cm0, myA0 * rcvA0);
            cm1 = fmaf(F1, cm1, myA1 * rcvA1);
            const float hm0 = O0 * tanhap(cm0);
            const float hm1 = O1 * tanhap(cm1);

            if (act) {
                // own-h for next step
                zw[nxt][m0][10 + u] = hm0;
                zw[nxt][m1][10 + u] = hm1;
                // staged x for t+1
                if (j < CH - 1)
                    *reinterpret_cast<float2*>(&zw[nxt][exE][exJ]) = xpre;
                // h out (next layer's input, or ys for top layer)
                float* dp = dstL + (size_t)t * BH + (b0 + m0) * H_ + u;
                dp[0]  = hm0;
                dp[10] = hm1;
                if (lastC && j == CH - 1) {
                    out[base_hn + (size_t)(l * B_ + b0 + m0) * H_ + u] = hm0;
                    out[base_hn + (size_t)(l * B_ + b0 + m1) * H_ + u] = hm1;
                    out[base_cn + (size_t)(l * B_ + b0 + m0) * H_ + u] = cm0;
                    out[base_cn + (size_t)(l * B_ + b0 + m1) * H_ + u] = cm1;
                }
            }
            __syncwarp();
        }

        // publish chunk c to the consumer
        if (l < L_ - 1) {
            __threadfence();
            __syncwarp();
            if (lane == 0) atomicExch(postc, c + 1);
        }
    }
}

extern "C" void kernel_launch(void* const* d_in, const int* in_sizes, int n_in,
                              void* d_out, int out_size) {
    const float* x   = (const float*)d_in[0];
    const float* hp  = (const float*)d_in[1];
    const float* cp  = (const float*)d_in[2];
    const float* Wih = (const float*)d_in[3];
    const float* Whh = (const float*)d_in[4];
    const float* bih = (const float*)d_in[5];
    const float* bhh = (const float*)d_in[6];
    float* out = (float*)d_out;

    reset_cnt_kernel<<<3, 1024>>>();                 // zero flags (replay-safe)
    dim3 grid(L_ * BPL);                             // 640 blocks, all resident
    dim3 block(NTH);                                 // 128 threads = 4 warps
    lstm_pipe15<<<grid, block>>>(x, hp, cp, Wih, Whh, bih, bhh, out);
}